// round 8
// baseline (speedup 1.0000x reference)
#include <cuda_runtime.h>
#include <cstdint>

#define NN 50000
#define EE 800000
#define FIN 128
#define HID 100
#define CL 16
#define LEAKYS 0.01f
#define NB_SCAN 196   // ceil(NN/256)
#define BN 112        // padded N for gemm1 (100 -> 112)
#define NTHR 224      // 16 ty x 14 tx

typedef unsigned long long ull;

// Scratch (alloc-free rule: __device__ globals). All fully rewritten each call.
__device__ int   g_cnt[NN];
__device__ int   g_off[NN];
__device__ int   g_cur[NN];
__device__ int   g_bsum[NB_SCAN];
__device__ float g_dinv[NN];
__device__ int   g_csrc[EE];
__device__ float g_Hs1[NN * HID];  // (x@W1) * dinv[row]
__device__ float g_Hs2[NN * CL];   // (leaky(out1)@W2) * dinv[row]

// ---------------- CSR build ----------------
__global__ void k_zero() {
    int i = blockIdx.x * blockDim.x + threadIdx.x;
    if (i < NN) g_cnt[i] = 0;
}
__global__ void k_hist(const int* __restrict__ ei) {
    int e = blockIdx.x * blockDim.x + threadIdx.x;
    if (e < EE) atomicAdd(&g_cnt[ei[EE + e]], 1);
}
__global__ void k_scanA() {
    __shared__ int s[256];
    int tid = threadIdx.x;
    int i = blockIdx.x * 256 + tid;
    int val = (i < NN) ? g_cnt[i] : 0;
    if (i < NN) g_dinv[i] = rsqrtf((float)val + 1.0f);
    s[tid] = val;
    __syncthreads();
#pragma unroll
    for (int off = 1; off < 256; off <<= 1) {
        int t = (tid >= off) ? s[tid - off] : 0;
        __syncthreads();
        s[tid] += t;
        __syncthreads();
    }
    if (i < NN) g_off[i] = s[tid] - val;
    if (tid == 255) g_bsum[blockIdx.x] = s[255];
}
__global__ void k_scanC() {
    __shared__ int red[256];
    int tid = threadIdx.x;
    int bid = blockIdx.x;
    int v = (tid < bid) ? g_bsum[tid] : 0;   // NB_SCAN <= 256
    red[tid] = v;
    __syncthreads();
#pragma unroll
    for (int off = 128; off >= 1; off >>= 1) {
        if (tid < off) red[tid] += red[tid + off];
        __syncthreads();
    }
    int base = red[0];
    int i = bid * 256 + tid;
    if (i < NN) {
        int o = g_off[i] + base;
        g_off[i] = o;
        g_cur[i] = o;
    }
}
__global__ void k_place(const int* __restrict__ ei) {
    int e = blockIdx.x * blockDim.x + threadIdx.x;
    if (e < EE) {
        int d = ei[EE + e];
        int pos = atomicAdd(&g_cur[d], 1);
        g_csrc[pos] = ei[e];
    }
}

// ---------------- GEMM1 (SIMT, packed f32x2, B duplicated in smem) ----------------
__device__ __forceinline__ void fma2(ull& d, ull a, ull b) {
    asm("fma.rn.f32x2 %0, %1, %2, %0;" : "+l"(d) : "l"(a), "l"(b));
}
__device__ __forceinline__ ull packdup(float a) {
    ull r;
    asm("mov.b64 %0, {%1, %1};" : "=l"(r) : "f"(a));
    return r;
}

// BM=128, BN=112, BK=16, 224 threads (ty 0..15 x tx 0..13), 8x8 per thread.
// As[k][m] natural floats; Bsd[k][n] value-duplicated f32x2.
__global__ __launch_bounds__(NTHR) void k_gemm1(const float* __restrict__ x,
                                                const float* __restrict__ W1) {
    __shared__ float As[2][16][128];   // 16 KB
    __shared__ ull   Bsd[2][16][BN];   // 28 KB
    int tid = threadIdx.x;
    int tx = tid % 14, ty = tid / 14;
    int m0 = blockIdx.x * 128;

    float4 stA[3];
    float  stB[8];

    // ---- prologue: tile 0 straight into smem ----
#pragma unroll
    for (int q = 0; q < 3; q++) {
        int i = tid + q * NTHR;
        if (i < 512) {
            int m = i >> 2, k4 = i & 3;
            int row = m0 + m;
            float4 v = (row < NN) ? *(const float4*)(x + (long)row * FIN + k4 * 4)
                                  : make_float4(0.f, 0.f, 0.f, 0.f);
            As[0][k4 * 4 + 0][m] = v.x;
            As[0][k4 * 4 + 1][m] = v.y;
            As[0][k4 * 4 + 2][m] = v.z;
            As[0][k4 * 4 + 3][m] = v.w;
        }
    }
#pragma unroll
    for (int q = 0; q < 8; q++) {
        int i = tid + q * NTHR;  // < 1792
        int k = i / BN, n = i % BN;
        float v = (n < HID) ? W1[k * HID + n] : 0.0f;
        Bsd[0][k][n] = packdup(v);
    }
    __syncthreads();

    ull acc[4][8];  // [m-pair][n]
#pragma unroll
    for (int p = 0; p < 4; p++)
#pragma unroll
        for (int n = 0; n < 8; n++) acc[p][n] = 0ull;

    for (int t = 0; t < 8; t++) {
        int buf = t & 1;
        if (t < 7) {
            int kk = (t + 1) * 16;
#pragma unroll
            for (int q = 0; q < 3; q++) {
                int i = tid + q * NTHR;
                if (i < 512) {
                    int m = i >> 2, k4 = i & 3;
                    int row = m0 + m;
                    stA[q] = (row < NN)
                                 ? *(const float4*)(x + (long)row * FIN + kk + k4 * 4)
                                 : make_float4(0.f, 0.f, 0.f, 0.f);
                }
            }
#pragma unroll
            for (int q = 0; q < 8; q++) {
                int i = tid + q * NTHR;
                int k = i / BN, n = i % BN;
                stB[q] = (n < HID) ? W1[(kk + k) * HID + n] : 0.0f;
            }
        }
#pragma unroll
        for (int k = 0; k < 16; k++) {
            const ull* ap = (const ull*)&As[buf][k][ty * 8];
            const ull* bp = &Bsd[buf][k][tx * 8];
            ull a[4] = {ap[0], ap[1], ap[2], ap[3]};
            ull b[8] = {bp[0], bp[1], bp[2], bp[3], bp[4], bp[5], bp[6], bp[7]};
#pragma unroll
            for (int p = 0; p < 4; p++)
#pragma unroll
                for (int n = 0; n < 8; n++) fma2(acc[p][n], a[p], b[n]);
        }
        if (t < 7) {
            int nb = buf ^ 1;
#pragma unroll
            for (int q = 0; q < 3; q++) {
                int i = tid + q * NTHR;
                if (i < 512) {
                    int m = i >> 2, k4 = i & 3;
                    As[nb][k4 * 4 + 0][m] = stA[q].x;
                    As[nb][k4 * 4 + 1][m] = stA[q].y;
                    As[nb][k4 * 4 + 2][m] = stA[q].z;
                    As[nb][k4 * 4 + 3][m] = stA[q].w;
                }
            }
#pragma unroll
            for (int q = 0; q < 8; q++) {
                int i = tid + q * NTHR;
                int k = i / BN, n = i % BN;
                Bsd[nb][k][n] = packdup(stB[q]);
            }
            __syncthreads();
        }
    }

    // ---- epilogue: rows ty*8+2p, ty*8+2p+1; cols tx*8..tx*8+7 (<100) ----
#pragma unroll
    for (int p = 0; p < 4; p++) {
        int row0 = m0 + ty * 8 + 2 * p;
        int row1 = row0 + 1;
        float di0 = (row0 < NN) ? g_dinv[row0] : 0.0f;
        float di1 = (row1 < NN) ? g_dinv[row1] : 0.0f;
#pragma unroll
        for (int n = 0; n < 8; n++) {
            int col = tx * 8 + n;
            if (col < HID) {
                float lo, hi;
                asm("mov.b64 {%0, %1}, %2;" : "=f"(lo), "=f"(hi) : "l"(acc[p][n]));
                if (row0 < NN) g_Hs1[(long)row0 * HID + col] = lo * di0;
                if (row1 < NN) g_Hs1[(long)row1 * HID + col] = hi * di1;
            }
        }
    }
}

// ---------------- Gather layer 1 + leaky + fused GEMM2 ----------------
__global__ __launch_bounds__(256) void k_gather1(const float* __restrict__ b1,
                                                 const float* __restrict__ W2,
                                                 const float* __restrict__ b2,
                                                 float* __restrict__ out) {
    __shared__ float W2s[HID][17];
    __shared__ float b1s[HID];
    __shared__ float b2s[CL];
    __shared__ float us[8][HID];
    int tid = threadIdx.x;
    for (int i = tid; i < HID * CL; i += 256) W2s[i / CL][i % CL] = W2[i];
    for (int i = tid; i < HID; i += 256) b1s[i] = b1[i];
    if (tid < CL) b2s[tid] = b2[tid];
    __syncthreads();

    int wid = tid >> 5, lane = tid & 31;
    int node = blockIdx.x * 8 + wid;
    if (node >= NN) return;

    int c0 = lane, c1 = lane + 32, c2 = lane + 64, c3 = lane + 96;
    bool has3 = c3 < HID;
    const float* selfrow = g_Hs1 + (long)node * HID;
    float a0 = selfrow[c0];
    float a1 = selfrow[c1];
    float a2 = selfrow[c2];
    float a3 = has3 ? selfrow[c3] : 0.0f;

    int start = g_off[node];
    int end = start + g_cnt[node];
    for (int j = start; j < end; j++) {
        int s = g_csrc[j];
        const float* r = g_Hs1 + (long)s * HID;
        a0 += r[c0];
        a1 += r[c1];
        a2 += r[c2];
        if (has3) a3 += r[c3];
    }

    float di = g_dinv[node];
    float o0 = b1s[c0] + di * a0;
    float o1 = b1s[c1] + di * a1;
    float o2 = b1s[c2] + di * a2;
    us[wid][c0] = o0 > 0.f ? o0 : LEAKYS * o0;
    us[wid][c1] = o1 > 0.f ? o1 : LEAKYS * o1;
    us[wid][c2] = o2 > 0.f ? o2 : LEAKYS * o2;
    if (has3) {
        float o3 = b1s[c3] + di * a3;
        us[wid][c3] = o3 > 0.f ? o3 : LEAKYS * o3;
    }
    __syncwarp();

    int c = lane & 15;
    int k0 = (lane >> 4) * 50;
    float p = 0.0f;
#pragma unroll 5
    for (int k = 0; k < 50; k++) {
        p += us[wid][k0 + k] * W2s[k0 + k][c];
    }
    p += __shfl_xor_sync(0xffffffffu, p, 16);
    if (lane < 16) {
        float h2 = di * p;
        g_Hs2[(long)node * CL + c] = h2;
        out[(long)node * CL + c] = b2s[c] + h2 * di;
    }
}

// ---------------- Gather layer 2 + log_softmax ----------------
__global__ __launch_bounds__(256) void k_gather2(float* __restrict__ out) {
    int t = blockIdx.x * 256 + threadIdx.x;
    int node = t >> 4;
    int c = t & 15;
    if (node >= NN) return;

    int start = g_off[node];
    int end = start + g_cnt[node];
    float acc = 0.0f;
    for (int j = start; j < end; j++) {
        int s = g_csrc[j];
        acc += g_Hs2[(long)s * CL + c];
    }
    float v = out[(long)node * CL + c] + g_dinv[node] * acc;

    float m = v;
#pragma unroll
    for (int msk = 8; msk >= 1; msk >>= 1)
        m = fmaxf(m, __shfl_xor_sync(0xffffffffu, m, msk, 16));
    float e = expf(v - m);
#pragma unroll
    for (int msk = 8; msk >= 1; msk >>= 1)
        e += __shfl_xor_sync(0xffffffffu, e, msk, 16);
    out[(long)node * CL + c] = v - m - logf(e);
}

extern "C" void kernel_launch(void* const* d_in, const int* in_sizes, int n_in,
                              void* d_out, int out_size) {
    const float* x  = (const float*)d_in[0];
    const float* W1 = (const float*)d_in[1];
    const float* b1 = (const float*)d_in[2];
    const float* W2 = (const float*)d_in[3];
    const float* b2 = (const float*)d_in[4];
    const int*   ei = (const int*)d_in[5];
    float* out = (float*)d_out;

    k_zero<<<NB_SCAN, 256>>>();
    k_hist<<<(EE + 255) / 256, 256>>>(ei);
    k_scanA<<<NB_SCAN, 256>>>();
    k_scanC<<<NB_SCAN, 256>>>();
    k_place<<<(EE + 255) / 256, 256>>>(ei);
    k_gemm1<<<(NN + 127) / 128, NTHR>>>(x, W1);
    k_gather1<<<(NN + 7) / 8, 256>>>(b1, W2, b2, out);
    k_gather2<<<(NN * 16 + 255) / 256, 256>>>(out);
}

// round 9
// speedup vs baseline: 1.0200x; 1.0200x over previous
#include <cuda_runtime.h>
#include <cstdint>

#define NN 50000
#define EE 800000
#define FIN 128
#define HID 100
#define CL 16
#define LEAKYS 0.01f
#define NB_SCAN 196   // ceil(NN/256)

typedef unsigned long long ull;

// Scratch (alloc-free rule: __device__ globals). All fully rewritten each call.
__device__ int   g_cnt[NN];
__device__ int   g_off[NN];
__device__ int   g_cur[NN];
__device__ int   g_bsum[NB_SCAN];
__device__ float g_dinv[NN];
__device__ int   g_csrc[EE];
__device__ float g_Hs1[NN * HID];  // (x@W1) * dinv[row]
__device__ float g_Hs2[NN * CL];   // (leaky(out1)@W2) * dinv[row]

// ---------------- CSR build ----------------
__global__ void k_zero() {
    int i = blockIdx.x * blockDim.x + threadIdx.x;
    if (i < NN) g_cnt[i] = 0;
}
__global__ void k_hist(const int* __restrict__ ei) {
    int e = blockIdx.x * blockDim.x + threadIdx.x;
    if (e < EE) atomicAdd(&g_cnt[ei[EE + e]], 1);
}
__global__ void k_scanA() {
    __shared__ int s[256];
    int tid = threadIdx.x;
    int i = blockIdx.x * 256 + tid;
    int val = (i < NN) ? g_cnt[i] : 0;
    if (i < NN) g_dinv[i] = rsqrtf((float)val + 1.0f);
    s[tid] = val;
    __syncthreads();
#pragma unroll
    for (int off = 1; off < 256; off <<= 1) {
        int t = (tid >= off) ? s[tid - off] : 0;
        __syncthreads();
        s[tid] += t;
        __syncthreads();
    }
    if (i < NN) g_off[i] = s[tid] - val;
    if (tid == 255) g_bsum[blockIdx.x] = s[255];
}
__global__ void k_scanC() {
    __shared__ int red[256];
    int tid = threadIdx.x;
    int bid = blockIdx.x;
    int v = (tid < bid) ? g_bsum[tid] : 0;   // NB_SCAN <= 256
    red[tid] = v;
    __syncthreads();
#pragma unroll
    for (int off = 128; off >= 1; off >>= 1) {
        if (tid < off) red[tid] += red[tid + off];
        __syncthreads();
    }
    int base = red[0];
    int i = bid * 256 + tid;
    if (i < NN) {
        int o = g_off[i] + base;
        g_off[i] = o;
        g_cur[i] = o;
    }
}
__global__ void k_place(const int* __restrict__ ei) {
    int e = blockIdx.x * blockDim.x + threadIdx.x;
    if (e < EE) {
        int d = ei[EE + e];
        int pos = atomicAdd(&g_cur[d], 1);
        g_csrc[pos] = ei[e];
    }
}

// ---------------- GEMM1 (SIMT, packed f32x2 FMA) — R6-proven version ----------------
__device__ __forceinline__ void fma2(ull& d, ull a, ull b) {
    asm("fma.rn.f32x2 %0, %1, %2, %0;" : "+l"(d) : "l"(a), "l"(b));
}
__device__ __forceinline__ ull packdup(float a) {
    ull r;
    asm("mov.b64 %0, {%1, %1};" : "=l"(r) : "f"(a));
    return r;
}

__global__ __launch_bounds__(256) void k_gemm1(const float* __restrict__ x,
                                               const float* __restrict__ W1) {
    __shared__ float As[2][16][128];  // [buf][k][m]
    __shared__ float Bs[2][16][128];  // [buf][k][n]
    int tid = threadIdx.x;
    int tx = tid & 15, ty = tid >> 4;
    int m0 = blockIdx.x * 128;

    int mA = tid >> 1;
    int kA = (tid & 1) * 8;
    int rowA = m0 + mA;
    bool okA = rowA < NN;
    const float* xrow = x + (long)rowA * FIN + kA;

    float4 rA0, rA1;
    float rB[8];
    {
        rA0 = okA ? *(const float4*)(xrow + 0) : make_float4(0, 0, 0, 0);
        rA1 = okA ? *(const float4*)(xrow + 4) : make_float4(0, 0, 0, 0);
#pragma unroll
        for (int i = 0; i < 8; i++) {
            int idx = tid + i * 256;
            int k = idx >> 7, n = idx & 127;
            rB[i] = (n < HID) ? W1[k * HID + n] : 0.0f;
        }
        float av[8] = {rA0.x, rA0.y, rA0.z, rA0.w, rA1.x, rA1.y, rA1.z, rA1.w};
#pragma unroll
        for (int j = 0; j < 8; j++) As[0][kA + j][mA] = av[j];
#pragma unroll
        for (int i = 0; i < 8; i++) {
            int idx = tid + i * 256;
            Bs[0][idx >> 7][idx & 127] = rB[i];
        }
    }
    __syncthreads();

    ull acc[8][4];  // [mi][nj-pair]
#pragma unroll
    for (int i = 0; i < 8; i++)
#pragma unroll
        for (int j = 0; j < 4; j++) acc[i][j] = 0ull;

    for (int t = 0; t < 8; t++) {
        int buf = t & 1;
        if (t < 7) {
            int kk = (t + 1) * 16;
            rA0 = okA ? *(const float4*)(xrow + kk + 0) : make_float4(0, 0, 0, 0);
            rA1 = okA ? *(const float4*)(xrow + kk + 4) : make_float4(0, 0, 0, 0);
#pragma unroll
            for (int i = 0; i < 8; i++) {
                int idx = tid + i * 256;
                int k = idx >> 7, n = idx & 127;
                rB[i] = (n < HID) ? W1[(kk + k) * HID + n] : 0.0f;
            }
        }
#pragma unroll
        for (int k = 0; k < 16; k++) {
            float4 a0 = *(const float4*)&As[buf][k][ty * 8];
            float4 a1 = *(const float4*)&As[buf][k][ty * 8 + 4];
            const ull* bp = (const ull*)&Bs[buf][k][tx * 8];
            ull b2[4] = {bp[0], bp[1], bp[2], bp[3]};
            float a[8] = {a0.x, a0.y, a0.z, a0.w, a1.x, a1.y, a1.z, a1.w};
#pragma unroll
            for (int i = 0; i < 8; i++) {
                ull a2 = packdup(a[i]);
#pragma unroll
                for (int j = 0; j < 4; j++) fma2(acc[i][j], a2, b2[j]);
            }
        }
        if (t < 7) {
            int nb = buf ^ 1;
            float av[8] = {rA0.x, rA0.y, rA0.z, rA0.w, rA1.x, rA1.y, rA1.z, rA1.w};
#pragma unroll
            for (int j = 0; j < 8; j++) As[nb][kA + j][mA] = av[j];
#pragma unroll
            for (int i = 0; i < 8; i++) {
                int idx = tid + i * 256;
                Bs[nb][idx >> 7][idx & 127] = rB[i];
            }
            __syncthreads();
        }
    }

#pragma unroll
    for (int i = 0; i < 8; i++) {
        int row = m0 + ty * 8 + i;
        if (row >= NN) continue;
        float di = g_dinv[row];
#pragma unroll
        for (int j = 0; j < 4; j++) {
            int col = tx * 8 + j * 2;
            if (col < HID) {
                float lo, hi;
                asm("mov.b64 {%0, %1}, %2;" : "=f"(lo), "=f"(hi) : "l"(acc[i][j]));
                *(float2*)(g_Hs1 + (long)row * HID + col) =
                    make_float2(lo * di, hi * di);
            }
        }
    }
}

// ---------------- Gather layer 1 + leaky + fused GEMM2 (2-way unrolled) ----------------
__global__ __launch_bounds__(256) void k_gather1(const float* __restrict__ b1,
                                                 const float* __restrict__ W2,
                                                 const float* __restrict__ b2,
                                                 float* __restrict__ out) {
    __shared__ float W2s[HID][17];
    __shared__ float b1s[HID];
    __shared__ float b2s[CL];
    __shared__ float us[8][HID];
    int tid = threadIdx.x;
    for (int i = tid; i < HID * CL; i += 256) W2s[i / CL][i % CL] = W2[i];
    for (int i = tid; i < HID; i += 256) b1s[i] = b1[i];
    if (tid < CL) b2s[tid] = b2[tid];
    __syncthreads();

    int wid = tid >> 5, lane = tid & 31;
    int node = blockIdx.x * 8 + wid;
    if (node >= NN) return;

    int c0 = lane, c1 = lane + 32, c2 = lane + 64, c3 = lane + 96;
    bool has3 = c3 < HID;
    const float* selfrow = g_Hs1 + (long)node * HID;
    float a0 = selfrow[c0];
    float a1 = selfrow[c1];
    float a2 = selfrow[c2];
    float a3 = has3 ? selfrow[c3] : 0.0f;

    int start = g_off[node];
    int cnt = g_cnt[node];
    int j = start;
    for (; j + 1 < start + cnt; j += 2) {
        int s0 = g_csrc[j];
        int s1 = g_csrc[j + 1];
        const float* r0 = g_Hs1 + (long)s0 * HID;
        const float* r1 = g_Hs1 + (long)s1 * HID;
        float t0 = r0[c0], t1 = r0[c1], t2 = r0[c2];
        float u0 = r1[c0], u1 = r1[c1], u2 = r1[c2];
        float t3 = has3 ? r0[c3] : 0.0f;
        float u3 = has3 ? r1[c3] : 0.0f;
        a0 += t0 + u0;
        a1 += t1 + u1;
        a2 += t2 + u2;
        a3 += t3 + u3;
    }
    if (j < start + cnt) {
        int s = g_csrc[j];
        const float* r = g_Hs1 + (long)s * HID;
        a0 += r[c0];
        a1 += r[c1];
        a2 += r[c2];
        if (has3) a3 += r[c3];
    }

    float di = g_dinv[node];
    float o0 = b1s[c0] + di * a0;
    float o1 = b1s[c1] + di * a1;
    float o2 = b1s[c2] + di * a2;
    us[wid][c0] = o0 > 0.f ? o0 : LEAKYS * o0;
    us[wid][c1] = o1 > 0.f ? o1 : LEAKYS * o1;
    us[wid][c2] = o2 > 0.f ? o2 : LEAKYS * o2;
    if (has3) {
        float o3 = b1s[c3] + di * a3;
        us[wid][c3] = o3 > 0.f ? o3 : LEAKYS * o3;
    }
    __syncwarp();

    int c = lane & 15;
    int k0 = (lane >> 4) * 50;
    float p = 0.0f;
#pragma unroll 5
    for (int k = 0; k < 50; k++) {
        p += us[wid][k0 + k] * W2s[k0 + k][c];
    }
    p += __shfl_xor_sync(0xffffffffu, p, 16);
    if (lane < 16) {
        float h2 = di * p;
        g_Hs2[(long)node * CL + c] = h2;
        out[(long)node * CL + c] = b2s[c] + h2 * di;
    }
}

// ---------------- Gather layer 2 + log_softmax (2-way unrolled) ----------------
__global__ __launch_bounds__(256) void k_gather2(float* __restrict__ out) {
    int t = blockIdx.x * 256 + threadIdx.x;
    int node = t >> 4;
    int c = t & 15;
    if (node >= NN) return;

    int start = g_off[node];
    int cnt = g_cnt[node];
    float acc = 0.0f;
    int j = start;
    for (; j + 1 < start + cnt; j += 2) {
        int s0 = g_csrc[j];
        int s1 = g_csrc[j + 1];
        float v0 = g_Hs2[(long)s0 * CL + c];
        float v1 = g_Hs2[(long)s1 * CL + c];
        acc += v0 + v1;
    }
    if (j < start + cnt) acc += g_Hs2[(long)g_csrc[j] * CL + c];

    float v = out[(long)node * CL + c] + g_dinv[node] * acc;

    float m = v;
#pragma unroll
    for (int msk = 8; msk >= 1; msk >>= 1)
        m = fmaxf(m, __shfl_xor_sync(0xffffffffu, m, msk, 16));
    float e = expf(v - m);
#pragma unroll
    for (int msk = 8; msk >= 1; msk >>= 1)
        e += __shfl_xor_sync(0xffffffffu, e, msk, 16);
    out[(long)node * CL + c] = v - m - logf(e);
}

extern "C" void kernel_launch(void* const* d_in, const int* in_sizes, int n_in,
                              void* d_out, int out_size) {
    const float* x  = (const float*)d_in[0];
    const float* W1 = (const float*)d_in[1];
    const float* b1 = (const float*)d_in[2];
    const float* W2 = (const float*)d_in[3];
    const float* b2 = (const float*)d_in[4];
    const int*   ei = (const int*)d_in[5];
    float* out = (float*)d_out;

    k_zero<<<NB_SCAN, 256>>>();
    k_hist<<<(EE + 255) / 256, 256>>>(ei);
    k_scanA<<<NB_SCAN, 256>>>();
    k_scanC<<<NB_SCAN, 256>>>();
    k_place<<<(EE + 255) / 256, 256>>>(ei);
    k_gemm1<<<(NN + 127) / 128, 256>>>(x, W1);
    k_gather1<<<(NN + 7) / 8, 256>>>(b1, W2, b2, out);
    k_gather2<<<(NN * 16 + 255) / 256, 256>>>(out);
}

// round 10
// speedup vs baseline: 1.5381x; 1.5080x over previous
#include <cuda_runtime.h>
#include <cstdint>

#define NN 50000
#define EE 800000
#define FIN 128
#define HID 100
#define CL 16
#define LEAKYS 0.01f
#define NB_SCAN 196   // ceil(NN/256)

typedef unsigned long long ull;

// Scratch (alloc-free rule: __device__ globals). All fully rewritten each call.
__device__ int   g_cnt[NN];
__device__ int   g_off[NN];
__device__ int   g_cur[NN];
__device__ int   g_bsum[NB_SCAN];
__device__ float g_dinv[NN];
__device__ int   g_csrc[EE];
__device__ float g_Hs1[NN * HID];  // (x@W1) * dinv[row]
__device__ float g_Hs2[NN * CL];   // (leaky(out1)@W2) * dinv[row]

// ---------------- CSR build ----------------
__global__ void k_hist(const int* __restrict__ ei) {
    int e = blockIdx.x * blockDim.x + threadIdx.x;
    if (e < EE) atomicAdd(&g_cnt[ei[EE + e]], 1);
}
__global__ void k_scanA() {
    __shared__ int s[256];
    int tid = threadIdx.x;
    int i = blockIdx.x * 256 + tid;
    int val = (i < NN) ? g_cnt[i] : 0;
    if (i < NN) g_dinv[i] = rsqrtf((float)val + 1.0f);
    s[tid] = val;
    __syncthreads();
#pragma unroll
    for (int off = 1; off < 256; off <<= 1) {
        int t = (tid >= off) ? s[tid - off] : 0;
        __syncthreads();
        s[tid] += t;
        __syncthreads();
    }
    if (i < NN) g_off[i] = s[tid] - val;
    if (tid == 255) g_bsum[blockIdx.x] = s[255];
}
__global__ void k_scanC() {
    __shared__ int red[256];
    int tid = threadIdx.x;
    int bid = blockIdx.x;
    int v = (tid < bid) ? g_bsum[tid] : 0;   // NB_SCAN <= 256
    red[tid] = v;
    __syncthreads();
#pragma unroll
    for (int off = 128; off >= 1; off >>= 1) {
        if (tid < off) red[tid] += red[tid + off];
        __syncthreads();
    }
    int base = red[0];
    int i = bid * 256 + tid;
    if (i < NN) {
        int o = g_off[i] + base;
        g_off[i] = o;
        g_cur[i] = o;
    }
}
__global__ void k_place(const int* __restrict__ ei) {
    int e = blockIdx.x * blockDim.x + threadIdx.x;
    if (e < EE) {
        int d = ei[EE + e];
        int pos = atomicAdd(&g_cur[d], 1);
        g_csrc[pos] = ei[e];
    }
}

// ---------------- GEMM1 (SIMT, packed f32x2 FMA) — R6-proven version ----------------
__device__ __forceinline__ void fma2(ull& d, ull a, ull b) {
    asm("fma.rn.f32x2 %0, %1, %2, %0;" : "+l"(d) : "l"(a), "l"(b));
}
__device__ __forceinline__ ull packdup(float a) {
    ull r;
    asm("mov.b64 %0, {%1, %1};" : "=l"(r) : "f"(a));
    return r;
}

__global__ __launch_bounds__(256) void k_gemm1(const float* __restrict__ x,
                                               const float* __restrict__ W1) {
    __shared__ float As[2][16][128];  // [buf][k][m]
    __shared__ float Bs[2][16][128];  // [buf][k][n]
    int tid = threadIdx.x;
    int tx = tid & 15, ty = tid >> 4;
    int m0 = blockIdx.x * 128;

    int mA = tid >> 1;
    int kA = (tid & 1) * 8;
    int rowA = m0 + mA;
    bool okA = rowA < NN;
    const float* xrow = x + (long)rowA * FIN + kA;

    float4 rA0, rA1;
    float rB[8];
    {
        rA0 = okA ? *(const float4*)(xrow + 0) : make_float4(0, 0, 0, 0);
        rA1 = okA ? *(const float4*)(xrow + 4) : make_float4(0, 0, 0, 0);
#pragma unroll
        for (int i = 0; i < 8; i++) {
            int idx = tid + i * 256;
            int k = idx >> 7, n = idx & 127;
            rB[i] = (n < HID) ? W1[k * HID + n] : 0.0f;
        }
        float av[8] = {rA0.x, rA0.y, rA0.z, rA0.w, rA1.x, rA1.y, rA1.z, rA1.w};
#pragma unroll
        for (int j = 0; j < 8; j++) As[0][kA + j][mA] = av[j];
#pragma unroll
        for (int i = 0; i < 8; i++) {
            int idx = tid + i * 256;
            Bs[0][idx >> 7][idx & 127] = rB[i];
        }
    }
    __syncthreads();

    ull acc[8][4];  // [mi][nj-pair]
#pragma unroll
    for (int i = 0; i < 8; i++)
#pragma unroll
        for (int j = 0; j < 4; j++) acc[i][j] = 0ull;

    for (int t = 0; t < 8; t++) {
        int buf = t & 1;
        if (t < 7) {
            int kk = (t + 1) * 16;
            rA0 = okA ? *(const float4*)(xrow + kk + 0) : make_float4(0, 0, 0, 0);
            rA1 = okA ? *(const float4*)(xrow + kk + 4) : make_float4(0, 0, 0, 0);
#pragma unroll
            for (int i = 0; i < 8; i++) {
                int idx = tid + i * 256;
                int k = idx >> 7, n = idx & 127;
                rB[i] = (n < HID) ? W1[(kk + k) * HID + n] : 0.0f;
            }
        }
#pragma unroll
        for (int k = 0; k < 16; k++) {
            float4 a0 = *(const float4*)&As[buf][k][ty * 8];
            float4 a1 = *(const float4*)&As[buf][k][ty * 8 + 4];
            const ull* bp = (const ull*)&Bs[buf][k][tx * 8];
            ull b2[4] = {bp[0], bp[1], bp[2], bp[3]};
            float a[8] = {a0.x, a0.y, a0.z, a0.w, a1.x, a1.y, a1.z, a1.w};
#pragma unroll
            for (int i = 0; i < 8; i++) {
                ull a2 = packdup(a[i]);
#pragma unroll
                for (int j = 0; j < 4; j++) fma2(acc[i][j], a2, b2[j]);
            }
        }
        if (t < 7) {
            int nb = buf ^ 1;
            float av[8] = {rA0.x, rA0.y, rA0.z, rA0.w, rA1.x, rA1.y, rA1.z, rA1.w};
#pragma unroll
            for (int j = 0; j < 8; j++) As[nb][kA + j][mA] = av[j];
#pragma unroll
            for (int i = 0; i < 8; i++) {
                int idx = tid + i * 256;
                Bs[nb][idx >> 7][idx & 127] = rB[i];
            }
            __syncthreads();
        }
    }

#pragma unroll
    for (int i = 0; i < 8; i++) {
        int row = m0 + ty * 8 + i;
        if (row >= NN) continue;
        float di = g_dinv[row];
#pragma unroll
        for (int j = 0; j < 4; j++) {
            int col = tx * 8 + j * 2;
            if (col < HID) {
                float lo, hi;
                asm("mov.b64 {%0, %1}, %2;" : "=f"(lo), "=f"(hi) : "l"(acc[i][j]));
                *(float2*)(g_Hs1 + (long)row * HID + col) =
                    make_float2(lo * di, hi * di);
            }
        }
    }
}

// ---------------- Gather layer 1 + leaky + fused GEMM2 ----------------
__global__ __launch_bounds__(256) void k_gather1(const float* __restrict__ b1,
                                                 const float* __restrict__ W2,
                                                 const float* __restrict__ b2,
                                                 float* __restrict__ out) {
    __shared__ float W2s[HID][17];
    __shared__ float b1s[HID];
    __shared__ float b2s[CL];
    __shared__ float us[8][HID];
    int tid = threadIdx.x;
    for (int i = tid; i < HID * CL; i += 256) W2s[i / CL][i % CL] = W2[i];
    for (int i = tid; i < HID; i += 256) b1s[i] = b1[i];
    if (tid < CL) b2s[tid] = b2[tid];
    __syncthreads();

    int wid = tid >> 5, lane = tid & 31;
    int node = blockIdx.x * 8 + wid;
    if (node >= NN) return;

    int c0 = lane, c1 = lane + 32, c2 = lane + 64, c3 = lane + 96;
    bool has3 = c3 < HID;
    const float* selfrow = g_Hs1 + (long)node * HID;
    float a0 = selfrow[c0];
    float a1 = selfrow[c1];
    float a2 = selfrow[c2];
    float a3 = has3 ? selfrow[c3] : 0.0f;

    int start = g_off[node];
    int end = start + g_cnt[node];
    for (int j = start; j < end; j++) {
        int s = g_csrc[j];
        const float* r = g_Hs1 + (long)s * HID;
        a0 += r[c0];
        a1 += r[c1];
        a2 += r[c2];
        if (has3) a3 += r[c3];
    }

    float di = g_dinv[node];
    float o0 = b1s[c0] + di * a0;
    float o1 = b1s[c1] + di * a1;
    float o2 = b1s[c2] + di * a2;
    us[wid][c0] = o0 > 0.f ? o0 : LEAKYS * o0;
    us[wid][c1] = o1 > 0.f ? o1 : LEAKYS * o1;
    us[wid][c2] = o2 > 0.f ? o2 : LEAKYS * o2;
    if (has3) {
        float o3 = b1s[c3] + di * a3;
        us[wid][c3] = o3 > 0.f ? o3 : LEAKYS * o3;
    }
    __syncwarp();

    int c = lane & 15;
    int k0 = (lane >> 4) * 50;
    float p = 0.0f;
#pragma unroll 5
    for (int k = 0; k < 50; k++) {
        p += us[wid][k0 + k] * W2s[k0 + k][c];
    }
    p += __shfl_xor_sync(0xffffffffu, p, 16);
    if (lane < 16) {
        float h2 = di * p;
        g_Hs2[(long)node * CL + c] = h2;
        out[(long)node * CL + c] = b2s[c] + h2 * di;
    }
}

// ---------------- Gather layer 2 + log_softmax ----------------
__global__ __launch_bounds__(256) void k_gather2(float* __restrict__ out) {
    int t = blockIdx.x * 256 + threadIdx.x;
    int node = t >> 4;
    int c = t & 15;
    if (node >= NN) return;

    int start = g_off[node];
    int end = start + g_cnt[node];
    float acc = 0.0f;
    for (int j = start; j < end; j++) {
        int s = g_csrc[j];
        acc += g_Hs2[(long)s * CL + c];
    }
    float v = out[(long)node * CL + c] + g_dinv[node] * acc;

    float m = v;
#pragma unroll
    for (int msk = 8; msk >= 1; msk >>= 1)
        m = fmaxf(m, __shfl_xor_sync(0xffffffffu, m, msk, 16));
    float e = expf(v - m);
#pragma unroll
    for (int msk = 8; msk >= 1; msk >>= 1)
        e += __shfl_xor_sync(0xffffffffu, e, msk, 16);
    out[(long)node * CL + c] = v - m - logf(e);
}

extern "C" void kernel_launch(void* const* d_in, const int* in_sizes, int n_in,
                              void* d_out, int out_size) {
    const float* x  = (const float*)d_in[0];
    const float* W1 = (const float*)d_in[1];
    const float* b1 = (const float*)d_in[2];
    const float* W2 = (const float*)d_in[3];
    const float* b2 = (const float*)d_in[4];
    const int*   ei = (const int*)d_in[5];
    float* out = (float*)d_out;

    // zero g_cnt via async memset (graph-capturable, no alloc)
    void* cnt_ptr = nullptr;
    cudaGetSymbolAddress(&cnt_ptr, g_cnt);
    cudaMemsetAsync(cnt_ptr, 0, NN * sizeof(int));

    k_hist<<<(EE + 255) / 256, 256>>>(ei);
    k_scanA<<<NB_SCAN, 256>>>();
    k_scanC<<<NB_SCAN, 256>>>();
    k_place<<<(EE + 255) / 256, 256>>>(ei);
    k_gemm1<<<(NN + 127) / 128, 256>>>(x, W1);
    k_gather1<<<(NN + 7) / 8, 256>>>(b1, W2, b2, out);
    k_gather2<<<(NN * 16 + 255) / 256, 256>>>(out);
}